// round 11
// baseline (speedup 1.0000x reference)
#include <cuda_runtime.h>
#include <cstdint>

#define D      512
#define BATCH  256
#define TOPK   2
#define NEXP   16
#define NPAIR  (BATCH * TOPK)
#define NH     2              // halves
#define HPAIR  (NPAIR / NH)   // 256 pairs per half
#define HB     (BATCH / NH)   // 128 batches per half
#define MAXCHH 32             // per-half worst-case sum ceil(M_e/16) = 31
#define NKS    2              // k-splits
#define KSL    (D / NKS)      // 256
#define XS_STRIDE 20          // 16 data + 4 pad floats
#define NGEMM_RAW (4 * MAXCHH * 4 * NKS)   // 1024 raw gemm blocks per half
#define NMIXH  (4 * HB)                    // 512 mix blocks per half

// ---------------- scratch ----------------
__device__ float g_iv[NKS * NPAIR * D];
__device__ float g_ov[NKS * NPAIR * D];
__device__ float g_dv[NKS * NPAIR * D];
__device__ float g_bv[NKS * NPAIR * D];
__device__ int   g_list_w[NPAIR];           // per-half segments [h*256, h*256+256)
__device__ int   g_list_b[NPAIR];
__device__ int   g_chunks_w[NH * MAXCHH];   // packed: start | e<<16 | rows<<24
__device__ int   g_chunks_b[NH * MAXCHH];
__device__ int   g_nch_w[NH], g_nch_b[NH];

// ---------------- kernel 0: per-half counting sort + chunk lists ----------------
__global__ void sort_kernel(const int* __restrict__ widx, const int* __restrict__ bidx) {
    __shared__ int cw[NH][NEXP], cb[NH][NEXP];
    __shared__ int offw[NH][NEXP + 1], offb[NH][NEXP + 1];
    __shared__ int pw[NH][NEXP], pb[NH][NEXP];
    int t = threadIdx.x;                    // 512 threads == global pair id
    int h = t >> 8;                         // pair half
    if (t < NH * NEXP) { cw[t >> 4][t & 15] = 0; cb[t >> 4][t & 15] = 0; }
    __syncthreads();
    int ew = widx[t];
    int eb = bidx[t];
    atomicAdd(&cw[h][ew], 1);
    atomicAdd(&cb[h][eb], 1);
    __syncthreads();
    if (t < 2 * NH) {                       // one thread per (half, type)
        int hh = t >> 1;
        bool isW = (t & 1) == 0;
        int* cnt = isW ? cw[hh] : cb[hh];
        int* off = isW ? offw[hh] : offb[hh];
        int* chk = (isW ? g_chunks_w : g_chunks_b) + hh * MAXCHH;
        int s = 0, n = 0;
        for (int e = 0; e < NEXP; e++) {
            off[e] = s;
            int c = cnt[e];
            for (int c0 = 0; c0 < c; c0 += 16) {
                int rows = min(16, c - c0);
                chk[n++] = (s + c0) | (e << 16) | (rows << 24);
            }
            s += c;
        }
        off[NEXP] = s;
        if (isW) g_nch_w[hh] = n; else g_nch_b[hh] = n;
    }
    __syncthreads();
    if (t < NH * NEXP) {
        pw[t >> 4][t & 15] = offw[t >> 4][t & 15];
        pb[t >> 4][t & 15] = offb[t >> 4][t & 15];
    }
    __syncthreads();
    int posw = atomicAdd(&pw[h][ew], 1);
    g_list_w[h * HPAIR + posw] = t;
    int posb = atomicAdd(&pb[h][eb], 1);
    g_list_b[h * HPAIR + posb] = t;
}

// ---------------- packed f32x2 helpers ----------------
__device__ __forceinline__ uint64_t dupf2(float w) {
    uint64_t r;
    asm("mov.b64 %0, {%1, %1};" : "=l"(r) : "r"(__float_as_uint(w)));
    return r;
}
__device__ __forceinline__ void fma2(uint64_t& acc, uint64_t a, uint64_t b) {
    asm("fma.rn.f32x2 %0, %1, %2, %0;" : "+l"(acc) : "l"(a), "l"(b));
}

// ---------------- gemm body: one 16-row chunk, one k-split, one bank ----------------
// decode g: tile = g&3, chunk = (g>>2)&31, z = g>>7 (bank = z&3, ks = z>>2)
__device__ __forceinline__ void gemm_body(
    int h, int g, float* xs,
    const float* __restrict__ x,
    const float* __restrict__ iw, const float* __restrict__ ow,
    const float* __restrict__ dw, const float* __restrict__ bb) {

    int tile  = g & 3;
    int chunk = (g >> 2) & (MAXCHH - 1);
    int z     = g >> 7;
    int bank  = z & 3;
    int ks    = z >> 2;
    int koff  = ks * KSL;
    bool isW  = bank < 3;
    int nch   = isW ? g_nch_w[h] : g_nch_b[h];
    if (chunk >= nch) return;

    int packed = ((isW ? g_chunks_w : g_chunks_b) + h * MAXCHH)[chunk];
    int s    = packed & 0xFFFF;            // local start within half
    int e    = (packed >> 16) & 0xFF;
    int rows = (packed >> 24) & 0xFF;

    const int* list = (isW ? g_list_w : g_list_b) + h * HPAIR;
    const float* W  = ((bank == 0) ? iw : (bank == 1) ? ow : (bank == 2) ? dw : bb)
                      + (size_t)e * D * D;
    float* out = ((bank == 0) ? g_iv : (bank == 1) ? g_ov : (bank == 2) ? g_dv : g_bv)
                 + (size_t)ks * NPAIR * D;

    int t   = threadIdx.x;
    int col = tile * 128 + t;

    // fill transposed x sub-chunk [16 rows x 256 kk]
    for (int idx2 = t; idx2 < 16 * KSL; idx2 += 128) {
        int m  = idx2 >> 8;
        int kk = idx2 & (KSL - 1);
        float val = 0.0f;
        if (m < rows) val = x[(list[s + m] >> 1) * D + koff + kk];
        xs[kk * XS_STRIDE + m] = val;
    }
    __syncthreads();

    uint64_t acc[8];
#pragma unroll
    for (int j = 0; j < 8; j++) acc[j] = 0ull;

    const float* Wc = W + (size_t)koff * D + col;
#pragma unroll 16
    for (int kk = 0; kk < KSL; kk++) {
        float w = Wc[kk * D];
        uint64_t ww = dupf2(w);
        const ulonglong2* row = (const ulonglong2*)&xs[kk * XS_STRIDE];
        ulonglong2 r0 = row[0];
        ulonglong2 r1 = row[1];
        ulonglong2 r2 = row[2];
        ulonglong2 r3 = row[3];
        fma2(acc[0], r0.x, ww);
        fma2(acc[1], r0.y, ww);
        fma2(acc[2], r1.x, ww);
        fma2(acc[3], r1.y, ww);
        fma2(acc[4], r2.x, ww);
        fma2(acc[5], r2.y, ww);
        fma2(acc[6], r3.x, ww);
        fma2(acc[7], r3.y, ww);
    }

#pragma unroll
    for (int j = 0; j < 8; j++) {
        float2 f2 = *reinterpret_cast<float2*>(&acc[j]);
        int r = 2 * j;
        if (r < rows)     out[(size_t)list[s + r] * D + col]     = f2.x;
        if (r + 1 < rows) out[(size_t)list[s + r + 1] * D + col] = f2.y;
    }
}

// ---------------- mix body: one (b, 128-row tile) ----------------
__device__ __forceinline__ void mix_body(
    int b, int tile, float* pool,
    const float* __restrict__ wp, const float* __restrict__ bp,
    float* __restrict__ outp) {

    int r0 = tile * 128;
    int t  = threadIdx.x;

    float* u = pool;                         // [D]
    float* v = pool + D;                     // [D]
    float4* sparams = (float4*)(pool + 2 * D);           // [128]
    float* red = pool + 2 * D + 512;                     // [20]

    // sum k-split partials of ov
    float4 u4 = make_float4(0.f, 0.f, 0.f, 0.f);
    float4 v4 = make_float4(0.f, 0.f, 0.f, 0.f);
#pragma unroll
    for (int ks = 0; ks < NKS; ks++) {
        const float* base = g_ov + (size_t)ks * NPAIR * D;
        float4 a = ((const float4*)(base + (size_t)(2 * b) * D))[t];
        float4 c = ((const float4*)(base + (size_t)(2 * b + 1) * D))[t];
        u4.x += a.x; u4.y += a.y; u4.z += a.z; u4.w += a.w;
        v4.x += c.x; v4.y += c.y; v4.z += c.z; v4.w += c.w;
    }
    ((float4*)u)[t] = u4;
    ((float4*)v)[t] = v4;

    float lu  = u4.x + u4.y + u4.z + u4.w;
    float lv  = v4.x + v4.y + v4.z + v4.w;
    float luu = u4.x * u4.x + u4.y * u4.y + u4.z * u4.z + u4.w * u4.w;
    float lvv = v4.x * v4.x + v4.y * v4.y + v4.z * v4.z + v4.w * v4.w;
    float luv = u4.x * v4.x + u4.y * v4.y + u4.z * v4.z + u4.w * v4.w;
#pragma unroll
    for (int sft = 16; sft > 0; sft >>= 1) {
        lu  += __shfl_xor_sync(0xffffffffu, lu, sft);
        lv  += __shfl_xor_sync(0xffffffffu, lv, sft);
        luu += __shfl_xor_sync(0xffffffffu, luu, sft);
        lvv += __shfl_xor_sync(0xffffffffu, lvv, sft);
        luv += __shfl_xor_sync(0xffffffffu, luv, sft);
    }
    int lane = t & 31, wrp = t >> 5;
    if (lane == 0) {
        red[wrp * 5 + 0] = lu; red[wrp * 5 + 1] = lv; red[wrp * 5 + 2] = luu;
        red[wrp * 5 + 3] = lvv; red[wrp * 5 + 4] = luv;
    }
    __syncthreads();
    float Su  = red[0] + red[5]  + red[10] + red[15];
    float Sv  = red[1] + red[6]  + red[11] + red[16];
    float Suu = red[2] + red[7]  + red[12] + red[17];
    float Svv = red[3] + red[8]  + red[13] + red[18];
    float Suv = red[4] + red[9]  + red[14] + red[19];

    {
        int i = r0 + t;
        float iv0 = 0.f, iv1 = 0.f, dv0 = 0.f, dv1 = 0.f;
#pragma unroll
        for (int ks = 0; ks < NKS; ks++) {
            size_t off = (size_t)ks * NPAIR * D;
            iv0 += g_iv[off + (size_t)(2 * b) * D + i];
            iv1 += g_iv[off + (size_t)(2 * b + 1) * D + i];
            dv0 += g_dv[off + (size_t)(2 * b) * D + i];
            dv1 += g_dv[off + (size_t)(2 * b + 1) * D + i];
        }
        float wp0 = wp[2 * b], wp1 = wp[2 * b + 1];
        float p = wp0 * iv0;
        float q = wp1 * iv1;
        float g = wp0 * dv0 + wp1 * dv1;
        const float invD = 1.0f / (float)D;
        float mean = (p * Su + q * Sv + g) * invD;
        float ex2  = (p * p * Suu + 2.0f * p * q * Suv + q * q * Svv
                      + 2.0f * g * (p * u[i] + q * v[i]) + g * g) * invD;
        float var  = ex2 - mean * mean;
        float rstd = rsqrtf(var + 1e-5f);
        float4 pr;
        pr.x = p * rstd;
        pr.y = q * rstd;
        pr.z = -mean * rstd;
        pr.w = g * rstd;
        sparams[t] = pr;
    }
    __syncthreads();

    float* orow = outp + ((size_t)b * D + r0) * D + (t << 2);

    if (wrp == tile) {
        int base = t << 2;
#pragma unroll 4
        for (int r = 0; r < 128; r++) {
            float4 P = sparams[r];
            float4 o;
            o.x = fmaf(P.y, v4.x, fmaf(P.x, u4.x, P.z));
            o.y = fmaf(P.y, v4.y, fmaf(P.x, u4.y, P.z));
            o.z = fmaf(P.y, v4.z, fmaf(P.x, u4.z, P.z));
            o.w = fmaf(P.y, v4.w, fmaf(P.x, u4.w, P.z));
            int dj = (r0 + r) - base;
            if (dj == 0) o.x += P.w;
            if (dj == 1) o.y += P.w;
            if (dj == 2) o.z += P.w;
            if (dj == 3) o.w += P.w;
            *(float4*)(orow + (size_t)r * D) = o;
        }
    } else {
#pragma unroll 4
        for (int r = 0; r < 128; r++) {
            float4 P = sparams[r];
            float4 o;
            o.x = fmaf(P.y, v4.x, fmaf(P.x, u4.x, P.z));
            o.y = fmaf(P.y, v4.y, fmaf(P.x, u4.y, P.z));
            o.z = fmaf(P.y, v4.z, fmaf(P.x, u4.z, P.z));
            o.w = fmaf(P.y, v4.w, fmaf(P.x, u4.w, P.z));
            *(float4*)(orow + (size_t)r * D) = o;
        }
    }

    // bmix (tile 0 only): bmix[b,:] = bp0*sum(bv0) + bp1*sum(bv1)
    if (tile == 0) {
        float bp0 = bp[2 * b], bp1 = bp[2 * b + 1];
        float4 b0 = make_float4(0.f, 0.f, 0.f, 0.f);
        float4 b1 = make_float4(0.f, 0.f, 0.f, 0.f);
#pragma unroll
        for (int ks = 0; ks < NKS; ks++) {
            const float* base = g_bv + (size_t)ks * NPAIR * D;
            float4 a = ((const float4*)(base + (size_t)(2 * b) * D))[t];
            float4 c = ((const float4*)(base + (size_t)(2 * b + 1) * D))[t];
            b0.x += a.x; b0.y += a.y; b0.z += a.z; b0.w += a.w;
            b1.x += c.x; b1.y += c.y; b1.z += c.z; b1.w += c.w;
        }
        float4 o;
        o.x = bp0 * b0.x + bp1 * b1.x;
        o.y = bp0 * b0.y + bp1 * b1.y;
        o.z = bp0 * b0.z + bp1 * b1.z;
        o.w = bp0 * b0.w + bp1 * b1.w;
        ((float4*)(outp + (size_t)BATCH * D * D + (size_t)b * D))[t] = o;
    }
}

// ---------------- kernel G0: gemm for half 0 ----------------
__global__ __launch_bounds__(128) void g0_kernel(
    const float* __restrict__ x,
    const float* __restrict__ iw, const float* __restrict__ ow,
    const float* __restrict__ dw, const float* __restrict__ bb) {
    __shared__ __align__(16) float xs[KSL * XS_STRIDE];   // 20KB
    gemm_body(0, blockIdx.x, xs, x, iw, ow, dw, bb);
}

// ---------------- kernel K2: co-scheduled mix(H0) + gemm(H1) ----------------
// bids [0, NMIXH): mix half 0 (tile = bid&3, b = bid>>2).
// bids [NMIXH, NMIXH+NGEMM_RAW): gemm half 1. No intra-kernel dependency:
// mix(H0) reads G0's completed outputs; gemm(H1) depends only on sort.
__global__ __launch_bounds__(128) void k2_kernel(
    const float* __restrict__ x,
    const float* __restrict__ iw, const float* __restrict__ ow,
    const float* __restrict__ dw, const float* __restrict__ bb,
    const float* __restrict__ wp, const float* __restrict__ bp,
    float* __restrict__ outp) {
    __shared__ __align__(16) float pool[KSL * XS_STRIDE];   // 20KB shared by both roles
    int bid = blockIdx.x;
    if (bid < NMIXH) {
        mix_body((bid >> 2), bid & 3, pool, wp, bp, outp);   // half 0: b in [0,128)
    } else {
        gemm_body(1, bid - NMIXH, pool, x, iw, ow, dw, bb);
    }
}

// ---------------- kernel M1: mix for half 1 ----------------
__global__ __launch_bounds__(128) void m1_kernel(
    const float* __restrict__ wp, const float* __restrict__ bp,
    float* __restrict__ outp) {
    __shared__ __align__(16) float pool[2 * D + 512 + 32];
    int bid = blockIdx.x;
    mix_body(HB + (bid >> 2), bid & 3, pool, wp, bp, outp);  // half 1: b in [128,256)
}

// ---------------- launch ----------------
extern "C" void kernel_launch(void* const* d_in, const int* in_sizes, int n_in,
                              void* d_out, int out_size) {
    const float* x    = (const float*)d_in[0];
    const float* wp   = (const float*)d_in[1];
    const float* bpr  = (const float*)d_in[2];
    const float* iw   = (const float*)d_in[3];
    const float* ow   = (const float*)d_in[4];
    const float* dw   = (const float*)d_in[5];
    const float* bb   = (const float*)d_in[6];
    const int*   widx = (const int*)d_in[7];
    const int*   bidx = (const int*)d_in[8];
    float* outp = (float*)d_out;

    sort_kernel<<<1, NPAIR>>>(widx, bidx);
    g0_kernel<<<NGEMM_RAW, 128>>>(x, iw, ow, dw, bb);
    k2_kernel<<<NMIXH + NGEMM_RAW, 128>>>(x, iw, ow, dw, bb, wp, bpr, outp);
    m1_kernel<<<NMIXH, 128>>>(wp, bpr, outp);
}

// round 12
// speedup vs baseline: 1.2725x; 1.2725x over previous
#include <cuda_runtime.h>
#include <cstdint>

#define D      512
#define BATCH  256
#define TOPK   2
#define NEXP   16
#define NPAIR  (BATCH * TOPK)
#define MAXCH  48          // worst-case sum ceil(M_e/16) over 16 experts = 48
#define XS_STRIDE 20       // 16 data + 4 pad floats; 80B rows, 16B-aligned
#define PF     8           // W prefetch pipeline depth

// ---------------- scratch ----------------
__device__ float g_iv[NPAIR * D];
__device__ float g_ov[NPAIR * D];
__device__ float g_dv[NPAIR * D];
__device__ float g_bv[NPAIR * D];
__device__ int   g_list_w[NPAIR];
__device__ int   g_list_b[NPAIR];
__device__ int   g_chunks_w[MAXCH];   // packed: start | e<<16 | rows<<24
__device__ int   g_chunks_b[MAXCH];
__device__ int   g_nch_w, g_nch_b;

// ---------------- kernel 0: counting sort + chunk work-list (r5-proven) ----------------
__global__ void sort_kernel(const int* __restrict__ widx, const int* __restrict__ bidx) {
    __shared__ int cw[NEXP], cb[NEXP], offw[NEXP + 1], offb[NEXP + 1], pw[NEXP], pb[NEXP];
    int t = threadIdx.x;                       // 512 threads == pair id
    if (t < NEXP) { cw[t] = 0; cb[t] = 0; }
    __syncthreads();
    int ew = widx[t];
    int eb = bidx[t];
    atomicAdd(&cw[ew], 1);
    atomicAdd(&cb[eb], 1);
    __syncthreads();
    if (t == 0) {
        int s = 0;
        for (int e = 0; e < NEXP; e++) { offw[e] = s; s += cw[e]; }
        offw[NEXP] = s;
        int n = 0;
        for (int e = 0; e < NEXP; e++)
            for (int c = offw[e]; c < offw[e + 1]; c += 16) {
                int rows = min(16, offw[e + 1] - c);
                g_chunks_w[n++] = c | (e << 16) | (rows << 24);
            }
        g_nch_w = n;
    }
    if (t == 32) {
        int s = 0;
        for (int e = 0; e < NEXP; e++) { offb[e] = s; s += cb[e]; }
        offb[NEXP] = s;
        int n = 0;
        for (int e = 0; e < NEXP; e++)
            for (int c = offb[e]; c < offb[e + 1]; c += 16) {
                int rows = min(16, offb[e + 1] - c);
                g_chunks_b[n++] = c | (e << 16) | (rows << 24);
            }
        g_nch_b = n;
    }
    __syncthreads();
    if (t < NEXP) { pw[t] = offw[t]; pb[t] = offb[t]; }
    __syncthreads();
    int posw = atomicAdd(&pw[ew], 1);
    g_list_w[posw] = t;
    int posb = atomicAdd(&pb[eb], 1);
    g_list_b[posb] = t;
}

// ---------------- packed f32x2 helpers ----------------
__device__ __forceinline__ uint64_t dupf2(float w) {
    uint64_t r;
    asm("mov.b64 %0, {%1, %1};" : "=l"(r) : "r"(__float_as_uint(w)));
    return r;
}
__device__ __forceinline__ void fma2(uint64_t& acc, uint64_t a, uint64_t b) {
    asm("fma.rn.f32x2 %0, %1, %2, %0;" : "+l"(acc) : "l"(a), "l"(b));
}

// ---------------- kernel 1: grouped GEMM (FFMA2 + explicit W prefetch pipeline) ------
// grid = (4 col-tiles of 128, MAXCH chunks, 4 banks), block = 128 threads. Thread owns
// 1 column + 16 rows (8 packed f32x2 accs). W loads run PF=8 iterations ahead in a
// register pipeline, guaranteeing 8 outstanding LDGs per warp regardless of ptxas
// scheduling => W stream latency structurally covered.
__global__ __launch_bounds__(128) void gemm_kernel(
    const float* __restrict__ x,
    const float* __restrict__ iw, const float* __restrict__ ow,
    const float* __restrict__ dw, const float* __restrict__ bb) {

    int bank = blockIdx.z;
    bool isW = bank < 3;
    int nch = isW ? g_nch_w : g_nch_b;
    if ((int)blockIdx.y >= nch) return;

    __shared__ __align__(16) float xs[D * XS_STRIDE];   // 40KB

    int packed = (isW ? g_chunks_w : g_chunks_b)[blockIdx.y];
    int s    = packed & 0xFFFF;
    int e    = (packed >> 16) & 0xFF;
    int rows = (packed >> 24) & 0xFF;

    const int* list = isW ? g_list_w : g_list_b;
    const float* W  = ((bank == 0) ? iw : (bank == 1) ? ow : (bank == 2) ? dw : bb)
                      + (size_t)e * D * D;
    float* out = (bank == 0) ? g_iv : (bank == 1) ? g_ov : (bank == 2) ? g_dv : g_bv;

    int t   = threadIdx.x;
    int col = blockIdx.x * 128 + t;

    // fill transposed x chunk (coalesced LDG; zero-pad rows >= rows)
    for (int idx2 = t; idx2 < 16 * D; idx2 += 128) {
        int m  = idx2 >> 9;
        int kk = idx2 & (D - 1);
        float val = 0.0f;
        if (m < rows) val = x[(list[s + m] >> 1) * D + kk];
        xs[kk * XS_STRIDE + m] = val;
    }
    __syncthreads();

    uint64_t acc[8];
#pragma unroll
    for (int j = 0; j < 8; j++) acc[j] = 0ull;

    const float* Wc = W + col;

    // prime the prefetch pipeline
    float wreg[PF];
#pragma unroll
    for (int i = 0; i < PF; i++) wreg[i] = Wc[i * D];

    for (int kk0 = 0; kk0 < D; kk0 += PF) {
        float wnext[PF];
        if (kk0 + PF < D) {
#pragma unroll
            for (int i = 0; i < PF; i++) wnext[i] = Wc[(kk0 + PF + i) * D];
        }
#pragma unroll
        for (int j = 0; j < PF; j++) {
            uint64_t ww = dupf2(wreg[j]);
            const ulonglong2* row = (const ulonglong2*)&xs[(kk0 + j) * XS_STRIDE];
            ulonglong2 r0 = row[0];
            ulonglong2 r1 = row[1];
            ulonglong2 r2 = row[2];
            ulonglong2 r3 = row[3];
            fma2(acc[0], r0.x, ww);
            fma2(acc[1], r0.y, ww);
            fma2(acc[2], r1.x, ww);
            fma2(acc[3], r1.y, ww);
            fma2(acc[4], r2.x, ww);
            fma2(acc[5], r2.y, ww);
            fma2(acc[6], r3.x, ww);
            fma2(acc[7], r3.y, ww);
        }
#pragma unroll
        for (int i = 0; i < PF; i++) wreg[i] = wnext[i];
    }

#pragma unroll
    for (int j = 0; j < 8; j++) {
        float2 f2 = *reinterpret_cast<float2*>(&acc[j]);
        int r = 2 * j;
        if (r < rows)     out[(size_t)list[s + r] * D + col]     = f2.x;
        if (r + 1 < rows) out[(size_t)list[s + r + 1] * D + col] = f2.y;
    }
}

// ---------------- kernel 2: mix + analytic LN + bmix (64-row tiles, 2048 blocks) ----
// Isolated change vs r5: 8 row-tiles of 64 per b => 2048 blocks (was 1024). mix was
// grid-quantization limited (occ 37%, L1 69.5%); doubling resident warps pushes the
// store path toward saturation. Math identical to r5/r8.
__global__ __launch_bounds__(128) void mix_ln_kernel(
    const float* __restrict__ wp, const float* __restrict__ bp,
    float* __restrict__ outp) {

    int b  = blockIdx.y;
    int r0 = blockIdx.x * 64;
    int t  = threadIdx.x;

    __shared__ float u[D], v[D];
    __shared__ __align__(16) float4 sparams[64];   // {pr, qr, c, gr}
    __shared__ float red[4][5];

    const float* u_g = g_ov + (size_t)(2 * b) * D;
    const float* v_g = g_ov + (size_t)(2 * b + 1) * D;
    float4 u4 = ((const float4*)u_g)[t];
    float4 v4 = ((const float4*)v_g)[t];
    ((float4*)u)[t] = u4;
    ((float4*)v)[t] = v4;

    float lu  = u4.x + u4.y + u4.z + u4.w;
    float lv  = v4.x + v4.y + v4.z + v4.w;
    float luu = u4.x * u4.x + u4.y * u4.y + u4.z * u4.z + u4.w * u4.w;
    float lvv = v4.x * v4.x + v4.y * v4.y + v4.z * v4.z + v4.w * v4.w;
    float luv = u4.x * v4.x + u4.y * v4.y + u4.z * v4.z + u4.w * v4.w;
#pragma unroll
    for (int sft = 16; sft > 0; sft >>= 1) {
        lu  += __shfl_xor_sync(0xffffffffu, lu, sft);
        lv  += __shfl_xor_sync(0xffffffffu, lv, sft);
        luu += __shfl_xor_sync(0xffffffffu, luu, sft);
        lvv += __shfl_xor_sync(0xffffffffu, lvv, sft);
        luv += __shfl_xor_sync(0xffffffffu, luv, sft);
    }
    int lane = t & 31, wrp = t >> 5;
    if (lane == 0) {
        red[wrp][0] = lu; red[wrp][1] = lv; red[wrp][2] = luu;
        red[wrp][3] = lvv; red[wrp][4] = luv;
    }
    __syncthreads();
    float Su  = red[0][0] + red[1][0] + red[2][0] + red[3][0];
    float Sv  = red[0][1] + red[1][1] + red[2][1] + red[3][1];
    float Suu = red[0][2] + red[1][2] + red[2][2] + red[3][2];
    float Svv = red[0][3] + red[1][3] + red[2][3] + red[3][3];
    float Suv = red[0][4] + red[1][4] + red[2][4] + red[3][4];

    if (t < 64) {
        int i = r0 + t;
        float wp0 = wp[2 * b], wp1 = wp[2 * b + 1];
        float p = wp0 * g_iv[(size_t)(2 * b) * D + i];
        float q = wp1 * g_iv[(size_t)(2 * b + 1) * D + i];
        float g = wp0 * g_dv[(size_t)(2 * b) * D + i]
                + wp1 * g_dv[(size_t)(2 * b + 1) * D + i];
        const float invD = 1.0f / (float)D;
        float mean = (p * Su + q * Sv + g) * invD;
        float ex2  = (p * p * Suu + 2.0f * p * q * Suv + q * q * Svv
                      + 2.0f * g * (p * u[i] + q * v[i]) + g * g) * invD;
        float var  = ex2 - mean * mean;
        float rstd = rsqrtf(var + 1e-5f);
        float4 pr;
        pr.x = p * rstd;
        pr.y = q * rstd;
        pr.z = -mean * rstd;
        pr.w = g * rstd;
        sparams[t] = pr;
    }
    __syncthreads();

    float* orow = outp + ((size_t)b * D + r0) * D + (t << 2);

    // diag cols 4t..4t+3 hit rows [r0, r0+64) iff t in [16*bx, 16*bx+16)
    if ((t >> 4) == blockIdx.x) {
        int base = t << 2;
#pragma unroll 4
        for (int r = 0; r < 64; r++) {
            float4 P = sparams[r];
            float4 o;
            o.x = fmaf(P.y, v4.x, fmaf(P.x, u4.x, P.z));
            o.y = fmaf(P.y, v4.y, fmaf(P.x, u4.y, P.z));
            o.z = fmaf(P.y, v4.z, fmaf(P.x, u4.z, P.z));
            o.w = fmaf(P.y, v4.w, fmaf(P.x, u4.w, P.z));
            int dj = (r0 + r) - base;
            if (dj == 0) o.x += P.w;
            if (dj == 1) o.y += P.w;
            if (dj == 2) o.z += P.w;
            if (dj == 3) o.w += P.w;
            *(float4*)(orow + (size_t)r * D) = o;
        }
    } else {
#pragma unroll 4
        for (int r = 0; r < 64; r++) {
            float4 P = sparams[r];
            float4 o;
            o.x = fmaf(P.y, v4.x, fmaf(P.x, u4.x, P.z));
            o.y = fmaf(P.y, v4.y, fmaf(P.x, u4.y, P.z));
            o.z = fmaf(P.y, v4.z, fmaf(P.x, u4.z, P.z));
            o.w = fmaf(P.y, v4.w, fmaf(P.x, u4.w, P.z));
            *(float4*)(orow + (size_t)r * D) = o;
        }
    }

    // bmix (row-tile 0 only): bmix[b,:] = bp0*bv0 + bp1*bv1
    if (blockIdx.x == 0) {
        float bp0 = bp[2 * b], bp1 = bp[2 * b + 1];
        float4 b0 = ((const float4*)(g_bv + (size_t)(2 * b) * D))[t];
        float4 b1 = ((const float4*)(g_bv + (size_t)(2 * b + 1) * D))[t];
        float4 o;
        o.x = bp0 * b0.x + bp1 * b1.x;
        o.y = bp0 * b0.y + bp1 * b1.y;
        o.z = bp0 * b0.z + bp1 * b1.z;
        o.w = bp0 * b0.w + bp1 * b1.w;
        ((float4*)(outp + (size_t)BATCH * D * D + (size_t)b * D))[t] = o;
    }
}

// ---------------- launch ----------------
extern "C" void kernel_launch(void* const* d_in, const int* in_sizes, int n_in,
                              void* d_out, int out_size) {
    const float* x    = (const float*)d_in[0];
    const float* wp   = (const float*)d_in[1];
    const float* bpr  = (const float*)d_in[2];
    const float* iw   = (const float*)d_in[3];
    const float* ow   = (const float*)d_in[4];
    const float* dw   = (const float*)d_in[5];
    const float* bb   = (const float*)d_in[6];
    const int*   widx = (const int*)d_in[7];
    const int*   bidx = (const int*)d_in[8];
    float* outp = (float*)d_out;

    sort_kernel<<<1, NPAIR>>>(widx, bidx);
    gemm_kernel<<<dim3(4, MAXCH, 4), 128>>>(x, iw, ow, dw, bb);
    mix_ln_kernel<<<dim3(8, BATCH), 128>>>(wp, bpr, outp);
}